// round 17
// baseline (speedup 1.0000x reference)
#include <cuda_runtime.h>
#include <cuda_bf16.h>
#include <math.h>

#define B_    128
#define T_    256
#define IN_   256
#define HID_  512
#define NG_   1536   // 3*HID
#define OUT_  64
#define WM_   (1536 * 256)   // u32 words per split matrix [1536][256]

// ---------------- scratch (static __device__, no allocation) ----------------
__device__ float    g_xg[(size_t)B_ * T_ * NG_];   // layer-0 input gates (bulk)
__device__ unsigned g_wsp[6][WM_];   // 0:hh0hi 1:hh0lo 2:hh1hi 3:hh1lo 4:ih1hi 5:ih1lo
__device__ unsigned g_hst[8][B_ * 256];  // [layer*4 + parity*2 + (0=hi,1=lo)][B][256]
__device__ float    g_hlast[B_ * HID_];  // final h1 for the head
__device__ unsigned g_ctr[1];

// ---------------- helpers ----------------------------------------------------
__device__ __forceinline__ unsigned f2tf32(float f) {
    unsigned u;
    asm("cvt.rna.tf32.f32 %0, %1;" : "=r"(u) : "f"(f));
    return u;
}
// hi = truncate-to-bf16(x); lo = rn_bf16(x - hi); hi+lo ~ x to 2^-17
__device__ __forceinline__ void split2(float x, unsigned& hi, unsigned& lo) {
    unsigned xb = __float_as_uint(x);
    hi = xb >> 16;
    float r = x - __uint_as_float(xb & 0xFFFF0000u);
    lo = (unsigned)__bfloat16_as_ushort(__float2bfloat16(r));
}
__device__ __forceinline__ void mma_bf16(float* d, const unsigned* a,
                                         unsigned b0, unsigned b1) {
    asm volatile(
        "mma.sync.aligned.m16n8k16.row.col.f32.bf16.bf16.f32 "
        "{%0,%1,%2,%3},{%4,%5,%6,%7},{%8,%9},{%0,%1,%2,%3};"
        : "+f"(d[0]), "+f"(d[1]), "+f"(d[2]), "+f"(d[3])
        : "r"(a[0]), "r"(a[1]), "r"(a[2]), "r"(a[3]), "r"(b0), "r"(b1));
}
__device__ __forceinline__ void ldmatrix_x4(unsigned* r, unsigned addr) {
    asm volatile("ldmatrix.sync.aligned.m8n8.x4.shared.b16 {%0,%1,%2,%3}, [%4];"
                 : "=r"(r[0]), "=r"(r[1]), "=r"(r[2]), "=r"(r[3]) : "r"(addr));
}

// ============================================================================
// Prep: split-convert a fp32 [1536][512] matrix into pair-packed hi/lo u32.
// ============================================================================
__global__ __launch_bounds__(256)
void splitw(const float* __restrict__ src, unsigned* __restrict__ dhi,
            unsigned* __restrict__ dlo)
{
    int i = blockIdx.x * 256 + threadIdx.x;   // word index < 1536*256
    float2 v = *(const float2*)(src + 2 * (size_t)i);
    unsigned h0, l0, h1, l1;
    split2(v.x, h0, l0);
    split2(v.y, h1, l1);
    dhi[i] = h0 | (h1 << 16);
    dlo[i] = l0 | (l1 << 16);
}

// ============================================================================
// tf32 tensor-core GEMM (proven): out = X @ W^T + bias  (layer-0 xg only)
// ============================================================================
#define BM 128
#define BN 128
#define BK 32
#define SP 36

__global__ __launch_bounds__(256, 2)
void gemm_tf32(const float* __restrict__ X, const float* __restrict__ W,
               const float* __restrict__ bias, float* __restrict__ out,
               int M, int N, int K)
{
    __shared__ unsigned Xs[BM][SP];
    __shared__ unsigned Ws[BN][SP];

    const int tid  = threadIdx.x;
    const int lane = tid & 31;
    const int wid  = tid >> 5;
    const int g    = lane >> 2;
    const int tg   = lane & 3;
    const int wm   = wid & 3;
    const int wn   = wid >> 2;
    const int m0   = blockIdx.y * BM;
    const int n0   = blockIdx.x * BN;
    const int m0w  = wm * 32;
    const int n0w  = wn * 64;

    const float* Xb = X + (size_t)m0 * K;
    const float* Wb = W + (size_t)n0 * K;

    float D[2][8][4];
#pragma unroll
    for (int mi = 0; mi < 2; mi++)
#pragma unroll
        for (int ni = 0; ni < 8; ni++)
#pragma unroll
            for (int q = 0; q < 4; q++) D[mi][ni][q] = 0.f;

    float4 px[4], pw[4];
#pragma unroll
    for (int l = 0; l < 4; l++) {
        int idx = l * 256 + tid;
        int row = idx >> 3, col = (idx & 7) * 4;
        px[l] = *(const float4*)(Xb + (size_t)row * K + col);
        pw[l] = *(const float4*)(Wb + (size_t)row * K + col);
    }

    for (int k0 = 0; k0 < K; k0 += BK) {
#pragma unroll
        for (int l = 0; l < 4; l++) {
            int idx = l * 256 + tid;
            int row = idx >> 3, col = (idx & 7) * 4;
            Xs[row][col + 0] = f2tf32(px[l].x);
            Xs[row][col + 1] = f2tf32(px[l].y);
            Xs[row][col + 2] = f2tf32(px[l].z);
            Xs[row][col + 3] = f2tf32(px[l].w);
            Ws[row][col + 0] = f2tf32(pw[l].x);
            Ws[row][col + 1] = f2tf32(pw[l].y);
            Ws[row][col + 2] = f2tf32(pw[l].z);
            Ws[row][col + 3] = f2tf32(pw[l].w);
        }
        __syncthreads();

        if (k0 + BK < K) {
#pragma unroll
            for (int l = 0; l < 4; l++) {
                int idx = l * 256 + tid;
                int row = idx >> 3, col = (idx & 7) * 4;
                px[l] = *(const float4*)(Xb + (size_t)row * K + k0 + BK + col);
                pw[l] = *(const float4*)(Wb + (size_t)row * K + k0 + BK + col);
            }
        }

#pragma unroll
        for (int kk = 0; kk < BK; kk += 8) {
            unsigned a[2][4];
#pragma unroll
            for (int mi = 0; mi < 2; mi++) {
                a[mi][0] = Xs[m0w + mi * 16 + g][kk + tg];
                a[mi][1] = Xs[m0w + mi * 16 + 8 + g][kk + tg];
                a[mi][2] = Xs[m0w + mi * 16 + g][kk + tg + 4];
                a[mi][3] = Xs[m0w + mi * 16 + 8 + g][kk + tg + 4];
            }
#pragma unroll
            for (int ni = 0; ni < 8; ni++) {
                unsigned b0 = Ws[n0w + ni * 8 + g][kk + tg];
                unsigned b1 = Ws[n0w + ni * 8 + g][kk + tg + 4];
#pragma unroll
                for (int mi = 0; mi < 2; mi++) {
                    asm volatile(
                        "mma.sync.aligned.m16n8k8.row.col.f32.tf32.tf32.f32 "
                        "{%0,%1,%2,%3}, {%4,%5,%6,%7}, {%8,%9}, {%0,%1,%2,%3};"
                        : "+f"(D[mi][ni][0]), "+f"(D[mi][ni][1]),
                          "+f"(D[mi][ni][2]), "+f"(D[mi][ni][3])
                        : "r"(a[mi][0]), "r"(a[mi][1]), "r"(a[mi][2]), "r"(a[mi][3]),
                          "r"(b0), "r"(b1));
                }
            }
        }
        __syncthreads();
    }

#pragma unroll
    for (int ni = 0; ni < 8; ni++) {
        int n = n0 + n0w + ni * 8 + 2 * tg;
        float bvx = bias[n], bvy = bias[n + 1];
#pragma unroll
        for (int mi = 0; mi < 2; mi++) {
            int mrow = m0 + m0w + mi * 16 + g;
            float2 o0 = make_float2(D[mi][ni][0] + bvx, D[mi][ni][1] + bvy);
            float2 o1 = make_float2(D[mi][ni][2] + bvx, D[mi][ni][3] + bvy);
            *(float2*)(out + (size_t)mrow * N + n)       = o0;
            *(float2*)(out + (size_t)(mrow + 8) * N + n) = o1;
        }
    }
}

// ============================================================================
// Fused 2-layer persistent GRU. Interval i: layer0 step i (i<256) and layer1
// step i-1 (i>=1); 257 intervals, one grid barrier each.
// 128 CTAs = 32 unit-tiles (16 units -> 48 gate rows) x 4 batch-tiles (32 rows).
// 8 warps = (n-half) x (k-quarter). A (h tiles) in smem via cp.async+ldmatrix,
// double-buffered by parity in g_hst. B (3 weight matrices) streamed as direct
// LDG fragments from pre-split g_wsp (L2-resident). 3-mma split per GEMM.
// ============================================================================
#define RBT 32
#define RUT 16
#define WP2 260
#define RED_P 50
#define OFF_H0HI 0
#define OFF_H0LO (OFF_H0HI + 32 * WP2)
#define OFF_H1HI (OFF_H0LO + 32 * WP2)
#define OFF_H1LO (OFF_H1HI + 32 * WP2)
#define OFF_RED0  (OFF_H1LO + 32 * WP2)
#define OFF_RED1A (OFF_RED0 + 4 * 32 * RED_P)
#define OFF_RED1B (OFF_RED1A + 4 * 32 * RED_P)
#define FUSED_SMEM_BYTES ((OFF_RED1B + 4 * 32 * RED_P) * 4)   // 209,920 B

__global__ __launch_bounds__(256)
void gru_fused(const float* __restrict__ xg0,
               const float* __restrict__ bhh0,
               const float* __restrict__ bih1,
               const float* __restrict__ bhh1,
               unsigned* __restrict__ ctr)
{
    extern __shared__ unsigned smu[];
    float* red0  = (float*)(smu + OFF_RED0);
    float* red1a = (float*)(smu + OFF_RED1A);
    float* red1b = (float*)(smu + OFF_RED1B);
    __shared__ float bs[144];   // 0-47 b_hh0 | 48-95 b_ih1 | 96-143 b_hh1

    const int tid = threadIdx.x;
    const int u0  = blockIdx.x * RUT;
    const int b0  = blockIdx.y * RBT;
    const unsigned nCTA = gridDim.x * gridDim.y;

    if (tid < 144) {
        int which = tid / 48, l = tid % 48;
        const float* src = (which == 0) ? bhh0 : (which == 1) ? bih1 : bhh1;
        bs[tid] = src[(l >> 4) * HID_ + u0 + (l & 15)];
    }

    const int lane = tid & 31;
    const int wid  = tid >> 5;
    const int g    = lane >> 2;      // 0..7
    const int c    = lane & 3;       // 0..3
    const int kq   = wid >> 1;       // k-quarter 0..3
    const int nh   = wid & 1;        // n-half 0/1
    const int wb0  = kq * 64;        // u32 word base of this quarter

    // A ldmatrix bases: 4 arrays (h0hi,h0lo,h1hi,h1lo) x 2 mi
    const int r8  = lane & 7;
    const int sel = lane >> 3;       // 0..3
    unsigned smu_sh = (unsigned)__cvta_generic_to_shared(smu);
    unsigned aB[4][2];
#pragma unroll
    for (int arr = 0; arr < 4; arr++)
#pragma unroll
        for (int mi = 0; mi < 2; mi++)
            aB[arr][mi] = smu_sh +
                ((arr * 32 * WP2 +
                  (mi * 16 + (sel & 1) * 8 + r8) * WP2 + (sel >> 1) * 4) << 2);

    // B row word-offsets (same row index for all 6 split matrices)
    unsigned rowIdx[3];
#pragma unroll
    for (int nt = 0; nt < 3; nt++) {
        int l = nh * 24 + nt * 8 + g;
        rowIdx[nt] = (unsigned)(((l >> 4) * HID_ + u0 + (l & 15)) * 256);
    }

    // epilogue ownership: 1 batch row, 2 adjacent units per thread
    const int ob = tid >> 3;          // 0..31
    const int oj = tid & 7;           // units 2oj, 2oj+1

    float2 hp0 = make_float2(0.f, 0.f);
    float2 hp1 = make_float2(0.f, 0.f);

    for (int i = 0; i < T_ + 1; i++) {
        // ---- stage h tiles ----
        if (i == 0) {
            for (int idx = tid; idx < 32 * 64; idx += 256) {
                int row = idx >> 6, q = idx & 63;
#pragma unroll
                for (int arr = 0; arr < 4; arr++)
                    *(uint4*)(smu + arr * 32 * WP2 + row * WP2 + q * 4) =
                        make_uint4(0, 0, 0, 0);
            }
        } else {
            const int s0 = ((i + 1) & 1) * 2;        // h0(i-1) slots
            for (int idx = tid; idx < 32 * 64; idx += 256) {
                int row = idx >> 6, q = idx & 63;
                unsigned goff = (unsigned)((b0 + row) * 256 + q * 4);
                unsigned dH = (unsigned)__cvta_generic_to_shared(
                    smu + OFF_H0HI + row * WP2 + q * 4);
                unsigned dL = (unsigned)__cvta_generic_to_shared(
                    smu + OFF_H0LO + row * WP2 + q * 4);
                asm volatile("cp.async.cg.shared.global [%0], [%1], 16;"
                             :: "r"(dH), "l"(&g_hst[s0 + 0][goff]));
                asm volatile("cp.async.cg.shared.global [%0], [%1], 16;"
                             :: "r"(dL), "l"(&g_hst[s0 + 1][goff]));
            }
            if (i == 1) {
                for (int idx = tid; idx < 32 * 64; idx += 256) {
                    int row = idx >> 6, q = idx & 63;
                    *(uint4*)(smu + OFF_H1HI + row * WP2 + q * 4) = make_uint4(0,0,0,0);
                    *(uint4*)(smu + OFF_H1LO + row * WP2 + q * 4) = make_uint4(0,0,0,0);
                }
            } else {
                const int s1 = 4 + (i & 1) * 2;      // h1(i-2) slots
                for (int idx = tid; idx < 32 * 64; idx += 256) {
                    int row = idx >> 6, q = idx & 63;
                    unsigned goff = (unsigned)((b0 + row) * 256 + q * 4);
                    unsigned dH = (unsigned)__cvta_generic_to_shared(
                        smu + OFF_H1HI + row * WP2 + q * 4);
                    unsigned dL = (unsigned)__cvta_generic_to_shared(
                        smu + OFF_H1LO + row * WP2 + q * 4);
                    asm volatile("cp.async.cg.shared.global [%0], [%1], 16;"
                                 :: "r"(dH), "l"(&g_hst[s1 + 0][goff]));
                    asm volatile("cp.async.cg.shared.global [%0], [%1], 16;"
                                 :: "r"(dL), "l"(&g_hst[s1 + 1][goff]));
                }
            }
            asm volatile("cp.async.commit_group;");
        }

        // ---- layer-0 xg prefetch for t=i (overlaps cp.async) ----
        float2 xr, xz, xn;
        if (i < T_) {
            size_t xb = ((size_t)(b0 + ob) * T_ + i) * NG_ + u0 + 2 * oj;
            xr = *(const float2*)(xg0 + xb);
            xz = *(const float2*)(xg0 + xb + 512);
            xn = *(const float2*)(xg0 + xb + 1024);
        }

        if (i > 0) asm volatile("cp.async.wait_group 0;");
        __syncthreads();

        // ---- mma: 3 GEMMs, m32 x n24 x 128 real k per warp ----
        float D0[2][3][4], D1a[2][3][4], D1b[2][3][4];
#pragma unroll
        for (int mi = 0; mi < 2; mi++)
#pragma unroll
            for (int nt = 0; nt < 3; nt++)
#pragma unroll
                for (int q = 0; q < 4; q++) {
                    D0[mi][nt][q] = 0.f; D1a[mi][nt][q] = 0.f; D1b[mi][nt][q] = 0.f;
                }

#pragma unroll 2
        for (int ki = 0; ki < 8; ki++) {
            unsigned koff = (unsigned)((wb0 + ki * 8) << 2);
            unsigned a0h[2][4], a0l[2][4], a1h[2][4], a1l[2][4];
#pragma unroll
            for (int mi = 0; mi < 2; mi++) {
                ldmatrix_x4(a0h[mi], aB[0][mi] + koff);
                ldmatrix_x4(a0l[mi], aB[1][mi] + koff);
                ldmatrix_x4(a1h[mi], aB[2][mi] + koff);
                ldmatrix_x4(a1l[mi], aB[3][mi] + koff);
            }
#pragma unroll
            for (int nt = 0; nt < 3; nt++) {
                unsigned idx = rowIdx[nt] + (unsigned)(wb0 + ki * 8) + (unsigned)c;
                unsigned b0h0 = __ldg(&g_wsp[0][idx]);
                unsigned b1h0 = __ldg(&g_wsp[0][idx + 4]);
                unsigned b0l0 = __ldg(&g_wsp[1][idx]);
                unsigned b1l0 = __ldg(&g_wsp[1][idx + 4]);
                unsigned b0h1 = __ldg(&g_wsp[2][idx]);
                unsigned b1h1 = __ldg(&g_wsp[2][idx + 4]);
                unsigned b0l1 = __ldg(&g_wsp[3][idx]);
                unsigned b1l1 = __ldg(&g_wsp[3][idx + 4]);
                unsigned b0hi = __ldg(&g_wsp[4][idx]);
                unsigned b1hi = __ldg(&g_wsp[4][idx + 4]);
                unsigned b0li = __ldg(&g_wsp[5][idx]);
                unsigned b1li = __ldg(&g_wsp[5][idx + 4]);
#pragma unroll
                for (int mi = 0; mi < 2; mi++) {
                    mma_bf16(D0[mi][nt],  a0h[mi], b0h0, b1h0);
                    mma_bf16(D0[mi][nt],  a0l[mi], b0h0, b1h0);
                    mma_bf16(D0[mi][nt],  a0h[mi], b0l0, b1l0);
                    mma_bf16(D1a[mi][nt], a0h[mi], b0hi, b1hi);
                    mma_bf16(D1a[mi][nt], a0l[mi], b0hi, b1hi);
                    mma_bf16(D1a[mi][nt], a0h[mi], b0li, b1li);
                    mma_bf16(D1b[mi][nt], a1h[mi], b0h1, b1h1);
                    mma_bf16(D1b[mi][nt], a1l[mi], b0h1, b1h1);
                    mma_bf16(D1b[mi][nt], a1h[mi], b0l1, b1l1);
                }
            }
        }

        // ---- write partials ----
#pragma unroll
        for (int mi = 0; mi < 2; mi++)
#pragma unroll
            for (int nt = 0; nt < 3; nt++) {
                int col = nh * 24 + nt * 8 + 2 * c;
                int r0 = kq * 32 + mi * 16 + g;
                *(float2*)&red0 [r0 * RED_P + col] = make_float2(D0[mi][nt][0],  D0[mi][nt][1]);
                *(float2*)&red0 [(r0 + 8) * RED_P + col] = make_float2(D0[mi][nt][2],  D0[mi][nt][3]);
                *(float2*)&red1a[r0 * RED_P + col] = make_float2(D1a[mi][nt][0], D1a[mi][nt][1]);
                *(float2*)&red1a[(r0 + 8) * RED_P + col] = make_float2(D1a[mi][nt][2], D1a[mi][nt][3]);
                *(float2*)&red1b[r0 * RED_P + col] = make_float2(D1b[mi][nt][0], D1b[mi][nt][1]);
                *(float2*)&red1b[(r0 + 8) * RED_P + col] = make_float2(D1b[mi][nt][2], D1b[mi][nt][3]);
            }
        __syncthreads();

        const int u = 2 * oj;
        const unsigned wpos = (unsigned)((b0 + ob) * 256 + (u0 >> 1) + oj);

        // ---- epilogue layer 0 (t0 = i) ----
        if (i < T_) {
            float2 sr = make_float2(bs[u],      bs[u + 1]);
            float2 sz = make_float2(bs[16 + u], bs[17 + u]);
            float2 sn = make_float2(bs[32 + u], bs[33 + u]);
#pragma unroll
            for (int q = 0; q < 4; q++) {
                const float* rp = red0 + (q * 32 + ob) * RED_P;
                float2 v;
                v = *(const float2*)(rp + u);      sr.x += v.x; sr.y += v.y;
                v = *(const float2*)(rp + 16 + u); sz.x += v.x; sz.y += v.y;
                v = *(const float2*)(rp + 32 + u); sn.x += v.x; sn.y += v.y;
            }
            float r0g = 1.f / (1.f + __expf(-(xr.x + sr.x)));
            float r1g = 1.f / (1.f + __expf(-(xr.y + sr.y)));
            float z0g = 1.f / (1.f + __expf(-(xz.x + sz.x)));
            float z1g = 1.f / (1.f + __expf(-(xz.y + sz.y)));
            float n0g = tanhf(xn.x + r0g * sn.x);
            float n1g = tanhf(xn.y + r1g * sn.y);
            float hv0 = (1.f - z0g) * n0g + z0g * hp0.x;
            float hv1 = (1.f - z1g) * n1g + z1g * hp0.y;
            unsigned h0w, l0w, h1w, l1w;
            split2(hv0, h0w, l0w);
            split2(hv1, h1w, l1w);
            const int w0 = (i & 1) * 2;
            g_hst[w0 + 0][wpos] = h0w | (h1w << 16);
            g_hst[w0 + 1][wpos] = l0w | (l1w << 16);
            hp0 = make_float2(hv0, hv1);
        }

        // ---- epilogue layer 1 (t1 = i-1) ----
        if (i >= 1) {
            float2 xr1 = make_float2(bs[48 + u],  bs[49 + u]);
            float2 xz1 = make_float2(bs[64 + u],  bs[65 + u]);
            float2 xn1 = make_float2(bs[80 + u],  bs[81 + u]);
            float2 hr1 = make_float2(bs[96 + u],  bs[97 + u]);
            float2 hz1 = make_float2(bs[112 + u], bs[113 + u]);
            float2 hn1 = make_float2(bs[128 + u], bs[129 + u]);
#pragma unroll
            for (int q = 0; q < 4; q++) {
                const float* ra = red1a + (q * 32 + ob) * RED_P;
                const float* rb = red1b + (q * 32 + ob) * RED_P;
                float2 v;
                v = *(const float2*)(ra + u);      xr1.x += v.x; xr1.y += v.y;
                v = *(const float2*)(ra + 16 + u); xz1.x += v.x; xz1.y += v.y;
                v = *(const float2*)(ra + 32 + u); xn1.x += v.x; xn1.y += v.y;
                v = *(const float2*)(rb + u);      hr1.x += v.x; hr1.y += v.y;
                v = *(const float2*)(rb + 16 + u); hz1.x += v.x; hz1.y += v.y;
                v = *(const float2*)(rb + 32 + u); hn1.x += v.x; hn1.y += v.y;
            }
            float r0g = 1.f / (1.f + __expf(-(xr1.x + hr1.x)));
            float r1g = 1.f / (1.f + __expf(-(xr1.y + hr1.y)));
            float z0g = 1.f / (1.f + __expf(-(xz1.x + hz1.x)));
            float z1g = 1.f / (1.f + __expf(-(xz1.y + hz1.y)));
            float n0g = tanhf(xn1.x + r0g * hn1.x);
            float n1g = tanhf(xn1.y + r1g * hn1.y);
            float hv0 = (1.f - z0g) * n0g + z0g * hp1.x;
            float hv1 = (1.f - z1g) * n1g + z1g * hp1.y;
            unsigned h0w, l0w, h1w, l1w;
            split2(hv0, h0w, l0w);
            split2(hv1, h1w, l1w);
            const int w1 = 4 + ((i + 1) & 1) * 2;
            g_hst[w1 + 0][wpos] = h0w | (h1w << 16);
            g_hst[w1 + 1][wpos] = l0w | (l1w << 16);
            hp1 = make_float2(hv0, hv1);
            if (i == T_) {
                float* dst = g_hlast + (size_t)(b0 + ob) * HID_ + u0 + u;
                dst[0] = hv0;
                dst[1] = hv1;
            }
        }
        __syncthreads();   // red/h-smem consumption done before next interval

        if (i < T_) {
            if (tid == 0) {
                __threadfence();
                atomicAdd(ctr, 1u);
                unsigned target = (unsigned)(i + 1) * nCTA;
                volatile unsigned* vc = ctr;
                while (*vc < target) { }
                __threadfence();
            }
            __syncthreads();
        }
    }
}

// ============================================================================
// Head: y[b,o] = g_hlast[b,:] . W_out[o,:] + b_out[o]
// ============================================================================
__global__ __launch_bounds__(64)
void out_proj(const float* __restrict__ Wout, const float* __restrict__ bout,
              float* __restrict__ y)
{
    __shared__ float hs[HID_];
    const int b = blockIdx.x;
    const float* h = g_hlast + (size_t)b * HID_;
    for (int i = threadIdx.x; i < HID_; i += 64) hs[i] = h[i];
    __syncthreads();

    const int o = threadIdx.x;
    float acc = bout[o];
    const float* w = Wout + (size_t)o * HID_;
#pragma unroll 4
    for (int k = 0; k < HID_; k += 4) {
        float4 wv = *(const float4*)(w + k);
        acc += hs[k] * wv.x + hs[k + 1] * wv.y + hs[k + 2] * wv.z + hs[k + 3] * wv.w;
    }
    y[b * OUT_ + o] = acc;
}

// ============================================================================
extern "C" void kernel_launch(void* const* d_in, const int* in_sizes, int n_in,
                              void* d_out, int out_size)
{
    (void)in_sizes; (void)n_in; (void)out_size;
    const float* x     = (const float*)d_in[0];
    const float* W_ih0 = (const float*)d_in[1];
    const float* W_hh0 = (const float*)d_in[2];
    const float* b_ih0 = (const float*)d_in[3];
    const float* b_hh0 = (const float*)d_in[4];
    const float* W_ih1 = (const float*)d_in[5];
    const float* W_hh1 = (const float*)d_in[6];
    const float* b_ih1 = (const float*)d_in[7];
    const float* b_hh1 = (const float*)d_in[8];
    const float* W_out = (const float*)d_in[9];
    const float* b_out = (const float*)d_in[10];
    float* y = (float*)d_out;

    float* xg;
    unsigned *ctr, *wsp;
    cudaGetSymbolAddress((void**)&xg, g_xg);
    cudaGetSymbolAddress((void**)&ctr, g_ctr);
    cudaGetSymbolAddress((void**)&wsp, g_wsp);

    cudaFuncSetAttribute(gru_fused, cudaFuncAttributeMaxDynamicSharedMemorySize,
                         FUSED_SMEM_BYTES);

    cudaMemsetAsync(ctr, 0, sizeof(unsigned));

    // one-time per launch: split-convert the three recurrent-path matrices
    splitw<<<WM_ / 256, 256>>>(W_hh0, wsp + 0 * WM_, wsp + 1 * WM_);
    splitw<<<WM_ / 256, 256>>>(W_hh1, wsp + 2 * WM_, wsp + 3 * WM_);
    splitw<<<WM_ / 256, 256>>>(W_ih1, wsp + 4 * WM_, wsp + 5 * WM_);

    // bulk layer-0 input gates
    gemm_tf32<<<dim3(NG_ / BN, (B_ * T_) / BM), 256>>>(
        x, W_ih0, b_ih0, xg, B_ * T_, NG_, IN_);

    // fused 2-layer recurrence
    gru_fused<<<dim3(HID_ / RUT, B_ / RBT), 256, FUSED_SMEM_BYTES>>>(
        xg, b_hh0, b_ih1, b_hh1, ctr);

    // head
    out_proj<<<B_, 64>>>(W_out, b_out, y);
}